// round 10
// baseline (speedup 1.0000x reference)
#include <cuda_runtime.h>
#include <cuda_bf16.h>
#include <cstdint>

// ---------------- problem constants ----------------
#define B_   16
#define C_   64
#define H_   192
#define W_   192
#define NPIX (H_ * W_)

// ---------------- tiling (R5 geometry) ----------------
#define TR 8                   // tile rows
#define TC 32                  // tile cols (256 px, 64 oc per tile)
#define HR 10                  // halo rows
#define HC 34                  // halo cols
#define ROWB  272              // 34 * 8 B (word pair e0,e1)
#define SLOTB (HR * ROWB)      // 2720 B per (kf,p) slot
#define IMGB  (16 * SLOTB)     // 43520 B per image (hi or lo)
#define SPLIT (2 * IMGB)       // 87040 B per x buffer
#define WRB   16384            // one weight-ring slot (1024 uint4)
#define SMEM_BYTES (2 * SPLIT + 2 * WRB)  // 206848 -> 1 CTA/SM
#define THREADS 384            // 8 compute warps + 4 fill warps
#define TPC 16                 // tiles per CTA (persistent)
#define XELEMS (32 * HR * HC)  // 10880 fill elements per tile
#define XCHUNK 1360            // per tap-window fill chunk (8 * 1360 = 10880)

// Pre-packed W fragments: [b][tap][kf][hl][mf][lane] uint4 (mma A-frag order)
__device__ uint4 g_wfrag[B_ * 9 * 4 * 2 * 4 * 32];

// ---------------- helpers ----------------
__device__ __forceinline__ uint32_t smem_u32(const void* p) {
    uint32_t a;
    asm("{ .reg .u64 t; cvta.to.shared.u64 t, %1; cvt.u32.u64 %0, t; }" : "=r"(a) : "l"(p));
    return a;
}
__device__ __forceinline__ uint32_t cvt2(float lo, float hi) {
    uint32_t r;
    asm("cvt.rn.satfinite.bf16x2.f32 %0, %1, %2;" : "=r"(r) : "f"(hi), "f"(lo));
    return r;
}
__device__ __forceinline__ void split2(float v0, float v1, uint32_t& h2, uint32_t& l2) {
    h2 = cvt2(v0, v1);
    float h0 = __uint_as_float(h2 << 16);
    float h1 = __uint_as_float(h2 & 0xFFFF0000u);
    l2 = cvt2(v0 - h0, v1 - h1);
}
__device__ __forceinline__ void sts32(uint32_t a, uint32_t v) {
    asm volatile("st.shared.b32 [%0], %1;" :: "r"(a), "r"(v) : "memory");
}
__device__ __forceinline__ void sts128(uint32_t a, uint4 v) {
    asm volatile("st.shared.v4.b32 [%0], {%1,%2,%3,%4};"
                 :: "r"(a), "r"(v.x), "r"(v.y), "r"(v.z), "r"(v.w) : "memory");
}
__device__ __forceinline__ void lds128(uint4& v, uint32_t a) {
    asm volatile("ld.shared.v4.b32 {%0,%1,%2,%3}, [%4];"
                 : "=r"(v.x), "=r"(v.y), "=r"(v.z), "=r"(v.w) : "r"(a));
}
__device__ __forceinline__ void mma16816(float* c, const uint4& a, uint32_t b0, uint32_t b1) {
    asm volatile(
        "mma.sync.aligned.m16n8k16.row.col.f32.bf16.bf16.f32 "
        "{%0,%1,%2,%3}, {%4,%5,%6,%7}, {%8,%9}, {%0,%1,%2,%3};"
        : "+f"(c[0]), "+f"(c[1]), "+f"(c[2]), "+f"(c[3])
        : "r"(a.x), "r"(a.y), "r"(a.z), "r"(a.w), "r"(b0), "r"(b1));
}

// ---------------- prep: interpolate + split + pack W fragments ----------------
__global__ void prep_w(const float* __restrict__ W0, const float* __restrict__ W1,
                       const float* __restrict__ DoT)
{
    const int tap = blockIdx.x;
    const int b   = blockIdx.y;
    const float d = DoT[b], od = 1.0f - d;

    const int t    = threadIdx.x;
    const int kf   = t >> 7;
    const int mf   = (t >> 5) & 3;
    const int lane = t & 31;
    const int m    = mf * 16 + (lane >> 2);
    const int k    = kf * 16 + (lane & 3) * 2;

    float v[4][2];
    #pragma unroll
    for (int r = 0; r < 4; r++) {
        const int oc = m + (r & 1) * 8;
        const int ci = k + (r >> 1) * 8;
        const size_t g0 = (size_t)(oc * C_ + ci) * 9 + tap;
        v[r][0] = od * W0[g0] + d * W1[g0];
        v[r][1] = od * W0[g0 + 9] + d * W1[g0 + 9];
    }
    uint4 hi, lo;
    uint32_t* hp = &hi.x;
    uint32_t* lp = &lo.x;
    #pragma unroll
    for (int r = 0; r < 4; r++) split2(v[r][0], v[r][1], hp[r], lp[r]);

    const size_t base = ((((size_t)(b * 9 + tap) * 4 + kf) * 2) * 4 + mf) * 32 + lane;
    g_wfrag[base]       = hi;
    g_wfrag[base + 128] = lo;
}

// ---------------- main kernel: warp-specialized + weight ring ----------------
__global__ __launch_bounds__(THREADS, 1)
void conv_mma(const float* __restrict__ x, float* __restrict__ y)
{
    extern __shared__ char smem[];
    const uint32_t sx    = smem_u32(smem);
    const uint32_t wring = sx + 2 * SPLIT;

    const int tid  = threadIdx.x;
    const int wid  = tid >> 5;
    const int lane = tid & 31;

    // CTA -> batch / tile range (144 CTAs = 16 batches x 9 CTAs; 16 tiles each)
    const int b    = blockIdx.x / 9;
    const int tib0 = (blockIdx.x % 9) * TPC;

    const float* xb = x + (size_t)b * C_ * NPIX;
    float* yb       = y + (size_t)b * C_ * NPIX;
    const uint4* wf = g_wfrag + (size_t)b * 9 * 1024;

    // ---- x fill: elements [j0, j1) of tile tib's halo into buffer buf ----
    auto fill_x = [&](int tib, int buf, int j0, int j1, int start, int stride) {
        const int hy0 = (tib / 6) * TR - 1;
        const int hx0 = (tib % 6) * TC - 1;
        const uint32_t sbuf = sx + (uint32_t)buf * SPLIT;
        for (int j = j0 + start; j < j1; j += stride) {
            const int ci2 = j / (HR * HC);
            const int rem = j - ci2 * (HR * HC);
            const int r   = rem / HC;
            const int c   = rem - r * HC;
            const int gy  = hy0 + r;
            const int gx  = hx0 + c;
            float v0 = 0.f, v1 = 0.f;
            if ((unsigned)gy < H_ && (unsigned)gx < W_) {
                const float* p = xb + (size_t)(2 * ci2) * NPIX + gy * W_ + gx;
                v0 = p[0];
                v1 = p[NPIX];
            }
            uint32_t h2, l2;
            split2(v0, v1, h2, l2);
            const int kfi = ci2 >> 3, l = ci2 & 7, pp = l & 3, e = l >> 2;
            const uint32_t off = (uint32_t)((kfi * 4 + pp) * SLOTB + r * ROWB + c * 8 + e * 4);
            sts32(sbuf + off, h2);
            sts32(sbuf + IMGB + off, l2);
        }
    };
    // ---- weight copy: tap's 1024 uint4 into ring slot ----
    auto fill_w = [&](int tap, int slot, int start, int stride) {
        const uint4* src = wf + tap * 1024;
        const uint32_t dst = wring + (uint32_t)slot * WRB;
        for (int i = start; i < 1024; i += stride) {
            uint4 v = src[i];
            sts128(dst + (uint32_t)i * 16, v);
        }
    };

    // ---- prologue: all threads fill x tile0 -> buf0, weights tap0 -> slot0 ----
    fill_x(tib0, 0, 0, XELEMS, tid, THREADS);
    fill_w(0, 0, tid, THREADS);

    const int p_  = lane & 3;
    const int q   = lane >> 2;
    const int row = wid;                 // compute warps: wid 0..7 = tile row
    const int ft  = tid - 256;           // fill warps: 0..127

    for (int t = 0; t < TPC; t++) {
        const int tib = tib0 + t;
        const int py0 = (tib / 6) * TR;
        const int px0 = (tib % 6) * TC;

        float acc[4][4][4];
        if (wid < 8) {
            #pragma unroll
            for (int mf = 0; mf < 4; mf++)
                #pragma unroll
                for (int cs = 0; cs < 4; cs++) {
                    acc[mf][cs][0] = 0.f; acc[mf][cs][1] = 0.f;
                    acc[mf][cs][2] = 0.f; acc[mf][cs][3] = 0.f;
                }
        }

        const uint32_t sbuf = sx + (uint32_t)(t & 1) * SPLIT;
        const uint32_t thr_base = sbuf + (uint32_t)(p_ * SLOTB + q * 8);

        for (int tap = 0; tap < 9; tap++) {
            __syncthreads();   // window boundary: w slot (g&1) full; at tap0 also x buf ready
            const int g = t * 9 + tap;

            if (wid < 8) {
                // ============ compute warps: tap g from smem ============
                const int ky = tap / 3;
                const int kx = tap - ky * 3;
                const uint32_t wslot = wring + (uint32_t)(g & 1) * WRB;
                const uint32_t tap_off = (uint32_t)((row + ky) * ROWB + kx * 8);

                #pragma unroll
                for (int kf = 0; kf < 4; kf++) {
                    const uint32_t wkb = wslot + (uint32_t)(kf * 256 + lane) * 16;
                    uint4 ah[4], al[4];
                    #pragma unroll
                    for (int mf = 0; mf < 4; mf++) {
                        lds128(ah[mf], wkb + (uint32_t)(mf * 32) * 16);
                        lds128(al[mf], wkb + (uint32_t)((128 + mf * 32)) * 16);
                    }
                    const uint32_t a_base = thr_base + tap_off + (uint32_t)(kf * 4 * SLOTB);

                    #pragma unroll
                    for (int cs = 0; cs < 4; cs++) {
                        const uint32_t ad = a_base + cs * 64;
                        uint32_t bh0, bh1, bl0, bl1;
                        asm volatile("ld.shared.v2.b32 {%0,%1}, [%2];"
                                     : "=r"(bh0), "=r"(bh1) : "r"(ad));
                        asm volatile("ld.shared.v2.b32 {%0,%1}, [%2];"
                                     : "=r"(bl0), "=r"(bl1) : "r"(ad + IMGB));
                        #pragma unroll
                        for (int mf = 0; mf < 4; mf++) mma16816(acc[mf][cs], ah[mf], bh0, bh1);
                        #pragma unroll
                        for (int mf = 0; mf < 4; mf++) mma16816(acc[mf][cs], al[mf], bh0, bh1);
                        #pragma unroll
                        for (int mf = 0; mf < 4; mf++) mma16816(acc[mf][cs], ah[mf], bl0, bl1);
                    }
                }
            } else {
                // ============ fill warps: produce window g+1 ============
                if (g + 1 < TPC * 9) {
                    fill_w((g + 1) % 9, (g + 1) & 1, ft, 128);
                }
                if (tap < 8 && t + 1 < TPC) {
                    fill_x(tib + 1, (t + 1) & 1, tap * XCHUNK, (tap + 1) * XCHUNK, ft, 128);
                }
            }
        }

        // ---- epilogue (compute warps; fill warps hit next window's barrier) ----
        if (wid < 8) {
            const int gy = py0 + row;
            #pragma unroll
            for (int mf = 0; mf < 4; mf++) {
                const int oc = mf * 16 + q;
                #pragma unroll
                for (int cs = 0; cs < 4; cs++) {
                    const int gx = px0 + cs * 8 + 2 * p_;
                    float2* o0 = (float2*)(yb + (size_t)oc * NPIX + gy * W_ + gx);
                    *o0 = make_float2(acc[mf][cs][0], acc[mf][cs][1]);
                    float2* o1 = (float2*)(yb + (size_t)(oc + 8) * NPIX + gy * W_ + gx);
                    *o1 = make_float2(acc[mf][cs][2], acc[mf][cs][3]);
                }
            }
        }
    }
}

// ---------------- launch ----------------
extern "C" void kernel_launch(void* const* d_in, const int* in_sizes, int n_in,
                              void* d_out, int out_size)
{
    const float* x   = (const float*)d_in[0];
    const float* DoT = (const float*)d_in[1];
    const float* W0  = (const float*)d_in[2];
    const float* W1  = (const float*)d_in[3];
    float* y = (float*)d_out;

    cudaFuncSetAttribute(conv_mma, cudaFuncAttributeMaxDynamicSharedMemorySize, SMEM_BYTES);

    prep_w<<<dim3(9, B_), 512>>>(W0, W1, DoT);
    // 2304 tiles total = 144 CTAs x 16 tiles; 9 CTAs per batch
    conv_mma<<<144, THREADS, SMEM_BYTES>>>(x, y);
}

// round 11
// speedup vs baseline: 2.7347x; 2.7347x over previous
#include <cuda_runtime.h>
#include <cuda_bf16.h>
#include <cstdint>

// ---------------- problem constants ----------------
#define B_   16
#define C_   64
#define H_   192
#define W_   192
#define NPIX (H_ * W_)

// ---------------- tiling (R5 geometry, quartered rows) ----------------
#define TR 4                 // tile rows
#define TC 32                // tile cols  (128 px, 64 oc per tile)
#define HR 6                 // halo rows
#define HC 34                // halo cols

// smem x layout per image: [slot = kf*4+p (16)][row (6)][col (34)][pair (2 words)]
#define ROWB  272            // 34 * 8 bytes per row
#define SLOTB 1648           // 6*272 = 1632 + 16 pad (bank stagger)
#define IMGB  (16 * SLOTB)   // 26368 bytes per image
#define SMEM_BYTES (2 * IMGB) // 52736 -> 4 CTAs/SM (210944 B total)

// Pre-packed W fragments: [b][tap][kf][hl][mf][lane] uint4 (mma A-frag order)
__device__ uint4 g_wfrag[B_ * 9 * 4 * 2 * 4 * 32];

// ---------------- helpers ----------------
__device__ __forceinline__ uint32_t smem_u32(const void* p) {
    uint32_t a;
    asm("{ .reg .u64 t; cvta.to.shared.u64 t, %1; cvt.u32.u64 %0, t; }" : "=r"(a) : "l"(p));
    return a;
}
__device__ __forceinline__ uint32_t cvt2(float lo, float hi) {
    uint32_t r;
    asm("cvt.rn.satfinite.bf16x2.f32 %0, %1, %2;" : "=r"(r) : "f"(hi), "f"(lo));
    return r;
}
__device__ __forceinline__ void split2(float v0, float v1, uint32_t& h2, uint32_t& l2) {
    h2 = cvt2(v0, v1);
    float h0 = __uint_as_float(h2 << 16);
    float h1 = __uint_as_float(h2 & 0xFFFF0000u);
    l2 = cvt2(v0 - h0, v1 - h1);
}
__device__ __forceinline__ void mma16816(float* c, const uint4& a, uint32_t b0, uint32_t b1) {
    asm volatile(
        "mma.sync.aligned.m16n8k16.row.col.f32.bf16.bf16.f32 "
        "{%0,%1,%2,%3}, {%4,%5,%6,%7}, {%8,%9}, {%0,%1,%2,%3};"
        : "+f"(c[0]), "+f"(c[1]), "+f"(c[2]), "+f"(c[3])
        : "r"(a.x), "r"(a.y), "r"(a.z), "r"(a.w), "r"(b0), "r"(b1));
}

// ---------------- prep: interpolate + split + pack W fragments ----------------
__global__ void prep_w(const float* __restrict__ W0, const float* __restrict__ W1,
                       const float* __restrict__ DoT)
{
    const int tap = blockIdx.x;
    const int b   = blockIdx.y;
    const float d = DoT[b], od = 1.0f - d;

    const int t    = threadIdx.x;
    const int kf   = t >> 7;
    const int mf   = (t >> 5) & 3;
    const int lane = t & 31;
    const int m    = mf * 16 + (lane >> 2);
    const int k    = kf * 16 + (lane & 3) * 2;

    float v[4][2];
    #pragma unroll
    for (int r = 0; r < 4; r++) {
        const int oc = m + (r & 1) * 8;
        const int ci = k + (r >> 1) * 8;
        const size_t g0 = (size_t)(oc * C_ + ci) * 9 + tap;
        v[r][0] = od * W0[g0] + d * W1[g0];
        v[r][1] = od * W0[g0 + 9] + d * W1[g0 + 9];
    }
    uint4 hi, lo;
    uint32_t* hp = &hi.x;
    uint32_t* lp = &lo.x;
    #pragma unroll
    for (int r = 0; r < 4; r++) split2(v[r][0], v[r][1], hp[r], lp[r]);

    const size_t base = ((((size_t)(b * 9 + tap) * 4 + kf) * 2) * 4 + mf) * 32 + lane;
    g_wfrag[base]       = hi;
    g_wfrag[base + 128] = lo;
}

// ---------------- main kernel (R5 structure, 128 threads, 4 CTAs/SM) ----------------
__global__ __launch_bounds__(128, 4)
void conv_mma(const float* __restrict__ x, float* __restrict__ y)
{
    extern __shared__ char smem[];
    const uint32_t sx = smem_u32(smem);

    const int tid  = threadIdx.x;
    const int wid  = tid >> 5;          // warp = tile row (0..3)
    const int lane = tid & 31;
    const int p_   = lane & 3;
    const int q    = lane >> 2;
    const int b    = blockIdx.y;
    const int py0  = (blockIdx.x / 6) * TR;
    const int px0  = (blockIdx.x % 6) * TC;

    const float* xb = x + (size_t)b * C_ * NPIX;

    // ---- fill smem: fp32 halo -> bf16 hi/lo split, fragment-friendly layout ----
    for (int idx = tid; idx < 32 * HR * HC; idx += 128) {
        const int ci2 = idx / (HR * HC);
        const int rem = idx - ci2 * (HR * HC);
        const int r   = rem / HC;
        const int c   = rem - r * HC;
        const int gy  = py0 - 1 + r;
        const int gx  = px0 - 1 + c;
        float v0 = 0.f, v1 = 0.f;
        if ((unsigned)gy < H_ && (unsigned)gx < W_) {
            const float* p = xb + (size_t)(2 * ci2) * NPIX + gy * W_ + gx;
            v0 = p[0];
            v1 = p[NPIX];
        }
        uint32_t h2, l2;
        split2(v0, v1, h2, l2);
        const int kfi = ci2 >> 3, l = ci2 & 7, pp = l & 3, e = l >> 2;
        const uint32_t off = (uint32_t)((kfi * 4 + pp) * SLOTB + r * ROWB + c * 8 + e * 4);
        asm volatile("st.shared.b32 [%0], %1;" :: "r"(sx + off),        "r"(h2) : "memory");
        asm volatile("st.shared.b32 [%0], %1;" :: "r"(sx + IMGB + off), "r"(l2) : "memory");
    }
    __syncthreads();

    float acc[4][4][4];
    #pragma unroll
    for (int mf = 0; mf < 4; mf++)
        #pragma unroll
        for (int cs = 0; cs < 4; cs++) {
            acc[mf][cs][0] = 0.f; acc[mf][cs][1] = 0.f;
            acc[mf][cs][2] = 0.f; acc[mf][cs][3] = 0.f;
        }

    const uint4* wf = g_wfrag + (size_t)(b * 9) * 1024;
    const uint32_t thr_base = sx + (uint32_t)(p_ * SLOTB + q * 8);

    for (int tap = 0; tap < 9; tap++) {
        const int ky = tap / 3;
        const int kx = tap - ky * 3;
        const uint32_t tap_off = (uint32_t)((wid + ky) * ROWB + kx * 8);
        const uint4* wft = wf + tap * 1024;

        #pragma unroll
        for (int kf = 0; kf < 4; kf++) {
            const uint4* wfk = wft + kf * 256;
            uint4 ah[4], al[4];
            #pragma unroll
            for (int mf = 0; mf < 4; mf++) {
                ah[mf] = wfk[mf * 32 + lane];
                al[mf] = wfk[128 + mf * 32 + lane];
            }
            const uint32_t a_base = thr_base + tap_off + (uint32_t)(kf * 4 * SLOTB);

            #pragma unroll
            for (int cs = 0; cs < 4; cs++) {
                const uint32_t addr = a_base + cs * 64;
                uint32_t bh0, bh1, bl0, bl1;
                asm volatile("ld.shared.v2.b32 {%0,%1}, [%2];"
                             : "=r"(bh0), "=r"(bh1) : "r"(addr));
                asm volatile("ld.shared.v2.b32 {%0,%1}, [%2];"
                             : "=r"(bl0), "=r"(bl1) : "r"(addr + IMGB));
                #pragma unroll
                for (int mf = 0; mf < 4; mf++) mma16816(acc[mf][cs], ah[mf], bh0, bh1);
                #pragma unroll
                for (int mf = 0; mf < 4; mf++) mma16816(acc[mf][cs], al[mf], bh0, bh1);
                #pragma unroll
                for (int mf = 0; mf < 4; mf++) mma16816(acc[mf][cs], ah[mf], bl0, bl1);
            }
        }
    }

    // ---- epilogue: D rows = oc, cols = pixels ----
    float* yb = y + (size_t)b * C_ * NPIX;
    const int gy = py0 + wid;
    #pragma unroll
    for (int mf = 0; mf < 4; mf++) {
        const int oc = mf * 16 + q;
        #pragma unroll
        for (int cs = 0; cs < 4; cs++) {
            const int gx = px0 + cs * 8 + p_ * 2;
            float2* o0 = (float2*)(yb + (size_t)oc * NPIX + gy * W_ + gx);
            *o0 = make_float2(acc[mf][cs][0], acc[mf][cs][1]);
            float2* o1 = (float2*)(yb + (size_t)(oc + 8) * NPIX + gy * W_ + gx);
            *o1 = make_float2(acc[mf][cs][2], acc[mf][cs][3]);
        }
    }
}

// ---------------- launch ----------------
extern "C" void kernel_launch(void* const* d_in, const int* in_sizes, int n_in,
                              void* d_out, int out_size)
{
    const float* x   = (const float*)d_in[0];
    const float* DoT = (const float*)d_in[1];
    const float* W0  = (const float*)d_in[2];
    const float* W1  = (const float*)d_in[3];
    float* y = (float*)d_out;

    cudaFuncSetAttribute(conv_mma, cudaFuncAttributeMaxDynamicSharedMemorySize, SMEM_BYTES);

    prep_w<<<dim3(9, B_), 512>>>(W0, W1, DoT);
    // tiles: 48 row-tiles x 6 col-tiles = 288 per batch
    conv_mma<<<dim3(288, B_), 128, SMEM_BYTES>>>(x, y);
}